// round 2
// baseline (speedup 1.0000x reference)
#include <cuda_runtime.h>
#include <cuda_fp16.h>

#define NMAX 50000
#define EMAX 800000
#define GMAXC 64
#define BN_EPS 1e-5f

// ---------- static device scratch (no allocation allowed) ----------
__device__ uint4  g_P4[(size_t)NMAX * 160];    // P: [n][o(20)][k(64)] fp16, o-row = 128B line
__device__ __half g_h[(size_t)EMAX * 64];      // h per edge, fp16
__device__ float  g_D[(size_t)NMAX * 20];      // b2 contribution per node
__device__ float  g_aggr[(size_t)NMAX * 20];   // scatter-add target
__device__ float  g_stats[160];                // [0..16): sum ea_i ; [16..152): upper-tri sum ea_i*ea_j
__device__ float  g_W1s[16 * 64];              // W1 with BN scale folded
__device__ float  g_shift[64];                 // BN shift (beta - mu*scale)
__device__ float  g_pool[GMAXC * 21];          // per-graph 20 sums + count

// ---------- k0: zero scratch ----------
__global__ void k0_zero(int N, int G) {
    int i = blockIdx.x * blockDim.x + threadIdx.x;
    int st = gridDim.x * blockDim.x;
    int na = N * 20;
    for (int t = i; t < na; t += st) g_aggr[t] = 0.f;
    for (int t = i; t < 160; t += st) g_stats[t] = 0.f;
    int np = G * 21;
    for (int t = i; t < np; t += st) g_pool[t] = 0.f;
}

// ---------- k1: edge_attr first/second moments ----------
__global__ void __launch_bounds__(256) k1_stats(const float* __restrict__ ea, int E) {
    __shared__ float sEA[128 * 17];
    int tid = threadIdx.x;
    int ji = 0, jj = 0;
    bool is_mean = false, is_pair = false;
    if (tid < 16) { ji = tid; is_mean = true; }
    else if (tid < 152) {
        int p = tid - 16, i = 0, c = 16;
        while (p >= c) { p -= c; i++; c--; }
        ji = i; jj = i + p; is_pair = true;
    }
    float acc = 0.f;
    int ntiles = (E + 127) >> 7;
    for (int t = blockIdx.x; t < ntiles; t += gridDim.x) {
        int base = t << 7;
        __syncthreads();
        for (int q = tid; q < 2048; q += blockDim.x) {
            int el = q >> 4, i = q & 15;
            int e = base + el;
            sEA[el * 17 + i] = (e < E) ? ea[(size_t)e * 16 + i] : 0.f;
        }
        __syncthreads();
        if (is_mean) {
            for (int e2 = 0; e2 < 128; e2++) acc += sEA[e2 * 17 + ji];
        } else if (is_pair) {
            for (int e2 = 0; e2 < 128; e2++) acc += sEA[e2 * 17 + ji] * sEA[e2 * 17 + jj];
        }
    }
    if (tid < 152) atomicAdd(&g_stats[tid], acc);
}

// ---------- k2: fold BN into W1s/shift ----------
__global__ void k2_prep(const float* __restrict__ W1, const float* __restrict__ gamma,
                        const float* __restrict__ beta, float Einv) {
    int k = threadIdx.x;
    if (k >= 64) return;
    float m[16], w[16];
#pragma unroll
    for (int i = 0; i < 16; i++) { m[i] = g_stats[i] * Einv; w[i] = W1[i * 64 + k]; }
    float mu = 0.f;
#pragma unroll
    for (int i = 0; i < 16; i++) mu += m[i] * w[i];
    float var = 0.f;
    int idx = 16;
    for (int i = 0; i < 16; i++)
        for (int j = i; j < 16; j++) {
            float c = g_stats[idx++] * Einv - m[i] * m[j];
            float ww = w[i] * w[j] * c;
            var += (i == j) ? ww : 2.f * ww;
        }
    float sc = gamma[k] * rsqrtf(var + BN_EPS);
    g_shift[k] = beta[k] - mu * sc;
#pragma unroll
    for (int i = 0; i < 16; i++) g_W1s[i * 64 + k] = w[i] * sc;
}

// ---------- k3: build P[n][o][k] fp16 ----------
// thread t: k = t&63, ob = t>>6 (0..3), owns o = ob+4j (j<5). W2 slice in registers.
__global__ void __launch_bounds__(256) k3_P(const float* __restrict__ x,
                                            const float* __restrict__ W2, int N) {
    __shared__ float sx[8 * 16];
    int t = threadIdx.x;
    int k = t & 63, ob = t >> 6;
    float w[5][16];
#pragma unroll
    for (int j = 0; j < 5; j++) {
        int o = ob + 4 * j;
#pragma unroll
        for (int i = 0; i < 16; i++) w[j][i] = W2[k * 320 + i * 20 + o];
    }
    __half* Ph = (__half*)g_P4;
    for (int n0 = blockIdx.x * 8; n0 < N; n0 += gridDim.x * 8) {
        int nn = min(8, N - n0);
        __syncthreads();
        for (int q = t; q < nn * 16; q += 256) sx[q] = x[(size_t)n0 * 16 + q];
        __syncthreads();
        for (int u = 0; u < nn; u++) {
            int n = n0 + u;
            float acc[5] = {0.f, 0.f, 0.f, 0.f, 0.f};
#pragma unroll
            for (int i = 0; i < 16; i++) {
                float xv = sx[u * 16 + i];
#pragma unroll
                for (int j = 0; j < 5; j++) acc[j] += xv * w[j][i];
            }
#pragma unroll
            for (int j = 0; j < 5; j++) {
                int o = ob + 4 * j;
                Ph[(size_t)n * 1280 + o * 64 + k] = __float2half(acc[j]);
            }
        }
    }
}

// ---------- k3b: D[n][o] = sum_i x[n,i] * b2[i*20+o] ----------
__global__ void k3b_D(const float* __restrict__ x, const float* __restrict__ b2, int N) {
    __shared__ float sb[320];
    for (int q = threadIdx.x; q < 320; q += blockDim.x) sb[q] = b2[q];
    __syncthreads();
    int id = blockIdx.x * blockDim.x + threadIdx.x;
    if (id >= N * 20) return;
    int n = id / 20, o = id % 20;
    const float* xr = x + (size_t)n * 16;
    float v = 0.f;
#pragma unroll
    for (int i = 0; i < 16; i++) v += xr[i] * sb[i * 20 + o];
    g_D[id] = v;
}

// ---------- k3c: h[e][k] = relu(ea[e]@W1s + shift) -> fp16 ----------
// warp per edge: lane owns k = 2*lane, 2*lane+1, weights in registers.
__global__ void __launch_bounds__(256) k3c_h(const float* __restrict__ ea, int E) {
    int lane = threadIdx.x & 31;
    int k0 = lane * 2;
    float w0[16], w1[16];
#pragma unroll
    for (int i = 0; i < 16; i++) { w0[i] = g_W1s[i * 64 + k0]; w1[i] = g_W1s[i * 64 + k0 + 1]; }
    float sh0 = g_shift[k0], sh1 = g_shift[k0 + 1];
    int nw = gridDim.x * (blockDim.x >> 5);
    int wi = blockIdx.x * (blockDim.x >> 5) + (threadIdx.x >> 5);
    for (int e = wi; e < E; e += nw) {
        const float4* e4 = (const float4*)ea + (size_t)e * 4;
        float ev[16];
        *(float4*)&ev[0] = e4[0]; *(float4*)&ev[4] = e4[1];
        *(float4*)&ev[8] = e4[2]; *(float4*)&ev[12] = e4[3];
        float h0 = sh0, h1 = sh1;
#pragma unroll
        for (int i = 0; i < 16; i++) { h0 += ev[i] * w0[i]; h1 += ev[i] * w1[i]; }
        ((__half2*)g_h)[(size_t)e * 32 + lane] = __floats2half2_rn(fmaxf(h0, 0.f), fmaxf(h1, 0.f));
    }
}

// ---------- k4: per-edge msg + scatter-add (8 lanes per edge) ----------
__global__ void __launch_bounds__(256) k4_edge(const int* __restrict__ ei, int E) {
    int tid = threadIdx.x;
    int r = tid & 7;
    int groups = gridDim.x * 32;
    for (int base = blockIdx.x * 32; base < E; base += groups) {
        int e = base + (tid >> 3);
        bool act = (e < E);
        int ec = act ? e : 0;
        int src = ei[ec], dst = ei[E + ec];
        uint4 hv = ((const uint4*)g_h)[(size_t)ec * 8 + r];
        float hf[8];
        {
            __half2* hp = (__half2*)&hv;
#pragma unroll
            for (int i = 0; i < 4; i++) {
                float2 f = __half22float2(hp[i]);
                hf[2 * i] = f.x; hf[2 * i + 1] = f.y;
            }
        }
        const uint4* Pn = g_P4 + (size_t)src * 160;
        float msg0 = 0.f, msg1 = 0.f, msg2 = 0.f;
#pragma unroll
        for (int o = 0; o < 20; o++) {
            uint4 pv = Pn[o * 8 + r];
            __half2* pp = (__half2*)&pv;
            float s = 0.f;
#pragma unroll
            for (int i = 0; i < 4; i++) {
                float2 f = __half22float2(pp[i]);
                s += hf[2 * i] * f.x + hf[2 * i + 1] * f.y;
            }
            s += __shfl_xor_sync(0xffffffffu, s, 4);
            s += __shfl_xor_sync(0xffffffffu, s, 2);
            s += __shfl_xor_sync(0xffffffffu, s, 1);
            if ((o & 7) == r) {
                if (o < 8) msg0 = s; else if (o < 16) msg1 = s; else msg2 = s;
            }
        }
        if (act) {
            const float* Dn = g_D + (size_t)src * 20;
            float* An = g_aggr + (size_t)dst * 20;
            atomicAdd(An + r, msg0 + Dn[r]);
            atomicAdd(An + 8 + r, msg1 + Dn[8 + r]);
            if (r < 4) atomicAdd(An + 16 + r, msg2 + Dn[16 + r]);
        }
    }
}

// ---------- k5: out = x@root_w + aggr + bias; pool by (sorted) batch ----------
// thread tau: c = tau/20 owns nodes [c*20, c*20+20), o = tau%20; local acc per graph run.
__global__ void k5_out(const float* __restrict__ x, const float* __restrict__ rw,
                       const float* __restrict__ bias, const int* __restrict__ batch, int N) {
    __shared__ float s_rw[320];
    __shared__ float s_b[20];
    int tid = threadIdx.x;
    for (int q = tid; q < 320; q += blockDim.x) s_rw[q] = rw[q];
    if (tid < 20) s_b[tid] = bias[tid];
    __syncthreads();
    int tau = blockIdx.x * blockDim.x + tid;
    int C = (N + 19) / 20;
    if (tau >= C * 20) return;
    int c = tau / 20, o = tau % 20;
    int curg = -1;
    float acc = 0.f, cnt = 0.f;
    for (int u = 0; u < 20; u++) {
        int n = c * 20 + u;
        if (n >= N) break;
        int g = batch[n];
        float v = s_b[o] + g_aggr[(size_t)n * 20 + o];
        const float* xr = x + (size_t)n * 16;
#pragma unroll
        for (int i = 0; i < 16; i++) v += xr[i] * s_rw[i * 20 + o];
        if (g != curg) {
            if (curg >= 0) {
                atomicAdd(&g_pool[curg * 21 + o], acc);
                if (o == 0) atomicAdd(&g_pool[curg * 21 + 20], cnt);
            }
            curg = g; acc = 0.f; cnt = 0.f;
        }
        acc += v; cnt += 1.f;
    }
    if (curg >= 0) {
        atomicAdd(&g_pool[curg * 21 + o], acc);
        if (o == 0) atomicAdd(&g_pool[curg * 21 + 20], cnt);
    }
}

// ---------- k6: critic head, one block per graph ----------
__global__ void __launch_bounds__(256) k6_critic(const float* __restrict__ a,
                                                 const float* __restrict__ Wc1,
                                                 const float* __restrict__ bc1,
                                                 const float* __restrict__ Wc2,
                                                 const float* __restrict__ bc2,
                                                 float* __restrict__ out) {
    int g = blockIdx.x;
    int tid = threadIdx.x;
    __shared__ float sz[28];
    __shared__ float sp[8];
    if (tid < 28) {
        if (tid < 20) {
            float cnt = g_pool[g * 21 + 20];
            float inv = 1.f / fmaxf(cnt, 1.f);
            sz[tid] = g_pool[g * 21 + tid] * inv;
        } else {
            sz[tid] = a[g * 8 + tid - 20];
        }
    }
    __syncthreads();
    float v = bc1[tid];
#pragma unroll
    for (int i = 0; i < 28; i++) v += sz[i] * Wc1[i * 256 + tid];
    v = fmaxf(v, 0.f);
    float p = v * Wc2[tid];
#pragma unroll
    for (int off = 16; off; off >>= 1) p += __shfl_xor_sync(0xffffffffu, p, off);
    if ((tid & 31) == 0) sp[tid >> 5] = p;
    __syncthreads();
    if (tid == 0) {
        float t = 0.f;
        for (int w = 0; w < 8; w++) t += sp[w];
        out[g] = t + bc2[0];
    }
}

// ---------- launch ----------
extern "C" void kernel_launch(void* const* d_in, const int* in_sizes, int n_in,
                              void* d_out, int out_size) {
    int N = in_sizes[0] / 16;
    int E = in_sizes[1] / 16;
    int G = out_size;  // output [G,1] float32

    const float *x = (const float*)d_in[0];
    const float *ea = (const float*)d_in[1];
    const float *a = (const float*)d_in[2];
    const float *W1, *gamma, *beta, *W2, *b2, *rw, *bias, *Wc1, *bc1, *Wc2, *bc2;
    const int *ei, *batch;

    bool dict_order = (n_in > 4 && in_sizes[3] == 2 * E);
    if (dict_order) {
        ei    = (const int*)d_in[3];
        batch = (const int*)d_in[4];
        W1    = (const float*)d_in[5];
        /* b1 = d_in[6] (cancels in BN) */
        gamma = (const float*)d_in[7];
        beta  = (const float*)d_in[8];
        W2    = (const float*)d_in[9];
        b2    = (const float*)d_in[10];
        rw    = (const float*)d_in[11];
        bias  = (const float*)d_in[12];
        Wc1   = (const float*)d_in[13];
        bc1   = (const float*)d_in[14];
        Wc2   = (const float*)d_in[15];
        bc2   = (const float*)d_in[16];
    } else {  // reference-signature order
        W1    = (const float*)d_in[3];
        /* b1 = d_in[4] */
        gamma = (const float*)d_in[5];
        beta  = (const float*)d_in[6];
        W2    = (const float*)d_in[7];
        b2    = (const float*)d_in[8];
        rw    = (const float*)d_in[9];
        bias  = (const float*)d_in[10];
        Wc1   = (const float*)d_in[11];
        bc1   = (const float*)d_in[12];
        Wc2   = (const float*)d_in[13];
        bc2   = (const float*)d_in[14];
        ei    = (const int*)d_in[15];
        batch = (const int*)d_in[16];
    }

    float* out = (float*)d_out;

    k0_zero<<<1024, 256>>>(N, G);
    {
        int ntiles = (E + 127) >> 7;
        int grid = ntiles < 1184 ? ntiles : 1184;
        k1_stats<<<grid, 256>>>(ea, E);
    }
    k2_prep<<<1, 64>>>(W1, gamma, beta, 1.0f / (float)E);
    k3_P<<<592, 256>>>(x, W2, N);
    k3b_D<<<(N * 20 + 255) / 256, 256>>>(x, b2, N);
    k3c_h<<<1184, 256>>>(ea, E);
    k4_edge<<<1184, 256>>>(ei, E);
    {
        int C = (N + 19) / 20;
        k5_out<<<(C * 20 + 255) / 256, 256>>>(x, rw, bias, batch, N);
    }
    k6_critic<<<G, 256>>>(a, Wc1, bc1, Wc2, bc2, out);
}